// round 2
// baseline (speedup 1.0000x reference)
#include <cuda_runtime.h>
#include <math.h>

static constexpr int kB = 4, kNA = 64, kT = 128, kD = 128, kH = 8, kL = 3;
static constexpr int kDFF = 512, kE = 65536, kNN = kT * kNA, kDH = kD / kH;
static constexpr int kRows = kB * kNA * kT;   // 32768

// ---------------- scratch (device globals; no runtime allocation) ----------
__device__ float g_x  [kRows * kD];
__device__ float g_e  [kRows * kD];
__device__ float g_q  [kRows * kD];
__device__ float g_k  [kRows * kD];
__device__ float g_v  [kRows * kD];
__device__ float g_ao [kRows * kD];
__device__ float g_h1 [kRows * kD];
__device__ float g_tmp[kRows * kD];
__device__ float g_ff [kRows * kDFF];
__device__ float g_s   [kB * kNN];
__device__ float g_gout[kB * kNN];
__device__ double g_red[2];

// ---------------- zero accumulators --------------------------------------
__global__ void zero_kernel() {
    int i = blockIdx.x * blockDim.x + threadIdx.x;
    if (i < kB * kNN) g_gout[i] = 0.f;
    if (i < 2) g_red[i] = 0.0;
}

// ---------------- hist projection + positional encoding -------------------
__global__ __launch_bounds__(128) void hist_pe_kernel(
        const float* __restrict__ feat, const float* __restrict__ w,
        const float* __restrict__ bias) {
    int row = blockIdx.x;
    int d = threadIdx.x;
    float f0 = feat[row * 3 + 0], f1 = feat[row * 3 + 1], f2 = feat[row * 3 + 2];
    float x = f0 * w[d] + f1 * w[kD + d] + f2 * w[2 * kD + d] + bias[d];
    g_x[row * kD + d] = x;
    int t = row % kT;
    int j = d >> 1;
    float freq = expf(-9.210340371976184f * (float)(2 * j) / (float)kD);
    float ang = (float)t * freq;
    float pe = (d & 1) ? cosf(ang) : sinf(ang);
    g_e[row * kD + d] = x + pe;
}

// ---------------- tiled SGEMM: C = A(MxK) * W(KxN) + bias [, relu] --------
template <bool RELU>
__global__ __launch_bounds__(256) void sgemm64(
        const float* __restrict__ A, const float* __restrict__ W,
        const float* __restrict__ bias, float* __restrict__ C,
        int M, int N, int K) {
    __shared__ float As[16][64];
    __shared__ float Bs[16][64];
    const int bm = blockIdx.y * 64, bn = blockIdx.x * 64;
    const int tid = threadIdx.x;
    const int tx = tid & 15, ty = tid >> 4;       // 16x16
    const int arow = tid >> 2, acol = (tid & 3) * 4;
    const int brow = tid >> 4, bcol = (tid & 15) * 4;
    float acc[4][4] = {};
    for (int k0 = 0; k0 < K; k0 += 16) {
        float4 a = *(const float4*)&A[(bm + arow) * K + k0 + acol];
        As[acol + 0][arow] = a.x;
        As[acol + 1][arow] = a.y;
        As[acol + 2][arow] = a.z;
        As[acol + 3][arow] = a.w;
        *(float4*)&Bs[brow][bcol] =
            *(const float4*)&W[(k0 + brow) * N + bn + bcol];
        __syncthreads();
#pragma unroll
        for (int kk = 0; kk < 16; kk++) {
            float4 af = *(const float4*)&As[kk][ty * 4];
            float4 bf = *(const float4*)&Bs[kk][tx * 4];
            float av[4] = {af.x, af.y, af.z, af.w};
            float bv[4] = {bf.x, bf.y, bf.z, bf.w};
#pragma unroll
            for (int i = 0; i < 4; i++)
#pragma unroll
                for (int j = 0; j < 4; j++)
                    acc[i][j] += av[i] * bv[j];
        }
        __syncthreads();
    }
#pragma unroll
    for (int i = 0; i < 4; i++) {
        int row = bm + ty * 4 + i;
#pragma unroll
        for (int j = 0; j < 4; j++) {
            int col = bn + tx * 4 + j;
            float v = acc[i][j] + bias[col];
            if (RELU) v = fmaxf(v, 0.f);
            C[row * N + col] = v;
        }
    }
}

// ---------------- fused attention per (b*n, h) -----------------------------
__global__ __launch_bounds__(128) void attn_kernel() {
    int bn = blockIdx.x;   // 0..B*NA-1
    int h  = blockIdx.y;   // 0..H-1
    int t  = threadIdx.x;  // query index
    __shared__ float sk[kT][kDH];
    __shared__ float sv[kT][kDH];
    const float* kp = g_k + (bn * kT + t) * kD + h * kDH;
    const float* vp = g_v + (bn * kT + t) * kD + h * kDH;
#pragma unroll
    for (int i = 0; i < 4; i++) {
        *(float4*)&sk[t][i * 4] = *(const float4*)&kp[i * 4];
        *(float4*)&sv[t][i * 4] = *(const float4*)&vp[i * 4];
    }
    float qr[16];
    const float* qp = g_q + (bn * kT + t) * kD + h * kDH;
#pragma unroll
    for (int i = 0; i < 4; i++)
        *(float4*)&qr[i * 4] = *(const float4*)&qp[i * 4];
    __syncthreads();

    const float scale = 0.25f;   // 1/sqrt(16)
    float m = -1e30f;
    for (int j = 0; j < kT; j++) {
        float a0 = 0, a1 = 0, a2 = 0, a3 = 0;
#pragma unroll
        for (int i = 0; i < 4; i++) {
            a0 += qr[i * 4 + 0] * sk[j][i * 4 + 0];
            a1 += qr[i * 4 + 1] * sk[j][i * 4 + 1];
            a2 += qr[i * 4 + 2] * sk[j][i * 4 + 2];
            a3 += qr[i * 4 + 3] * sk[j][i * 4 + 3];
        }
        m = fmaxf(m, (a0 + a1 + a2 + a3) * scale);
    }
    float sum = 0.f;
    float oacc[16];
#pragma unroll
    for (int i = 0; i < 16; i++) oacc[i] = 0.f;
    for (int j = 0; j < kT; j++) {
        float a0 = 0, a1 = 0, a2 = 0, a3 = 0;
#pragma unroll
        for (int i = 0; i < 4; i++) {
            a0 += qr[i * 4 + 0] * sk[j][i * 4 + 0];
            a1 += qr[i * 4 + 1] * sk[j][i * 4 + 1];
            a2 += qr[i * 4 + 2] * sk[j][i * 4 + 2];
            a3 += qr[i * 4 + 3] * sk[j][i * 4 + 3];
        }
        float p = expf((a0 + a1 + a2 + a3) * scale - m);
        sum += p;
#pragma unroll
        for (int i = 0; i < 16; i++) oacc[i] += p * sv[j][i];
    }
    float inv = 1.f / sum;
    float* op = g_ao + (bn * kT + t) * kD + h * kDH;
#pragma unroll
    for (int i = 0; i < 16; i++) op[i] = oacc[i] * inv;
}

// ---------------- fused residual + layernorm (rows of 128) -----------------
__global__ __launch_bounds__(128) void ln_kernel(
        const float* __restrict__ a, const float* __restrict__ r,
        const float* __restrict__ g, const float* __restrict__ b,
        float* __restrict__ out) {
    int row = blockIdx.x, t = threadIdx.x;
    float v = a[row * kD + t] + r[row * kD + t];
    __shared__ float ws[4];
    __shared__ float bc;
    float s = v;
#pragma unroll
    for (int o = 16; o > 0; o >>= 1) s += __shfl_xor_sync(~0u, s, o);
    if ((t & 31) == 0) ws[t >> 5] = s;
    __syncthreads();
    if (t == 0) bc = ws[0] + ws[1] + ws[2] + ws[3];
    __syncthreads();
    float mean = bc * (1.f / kD);
    float dv = v - mean;
    s = dv * dv;
#pragma unroll
    for (int o = 16; o > 0; o >>= 1) s += __shfl_xor_sync(~0u, s, o);
    if ((t & 31) == 0) ws[t >> 5] = s;
    __syncthreads();
    if (t == 0) bc = ws[0] + ws[1] + ws[2] + ws[3];
    __syncthreads();
    float var = bc * (1.f / kD);
    out[row * kD + t] = dv * rsqrtf(var + 1e-5f) * g[t] + b[t];
}

// ---------------- node score: s = <out_e_row, x_row> -----------------------
__global__ __launch_bounds__(128) void s_kernel() {
    int row = blockIdx.x, t = threadIdx.x;
    float p = g_e[row * kD + t] * g_x[row * kD + t];
    __shared__ float ws[4];
#pragma unroll
    for (int o = 16; o > 0; o >>= 1) p += __shfl_xor_sync(~0u, p, o);
    if ((t & 31) == 0) ws[t >> 5] = p;
    __syncthreads();
    if (t == 0) {
        float tot = ws[0] + ws[1] + ws[2] + ws[3];
        int b = row / (kNA * kT);
        int rem = row % (kNA * kT);
        int n = rem / kT, tt = rem % kT;
        g_s[b * kNN + tt * kNA + n] = tot;
    }
}

// ---------------- edge segment-sum ----------------------------------------
__global__ void edge_kernel(const int* __restrict__ ei,
                            const float* __restrict__ ew) {
    int idx = blockIdx.x * blockDim.x + threadIdx.x;
    if (idx >= kB * kE) return;
    int b = idx / kE, e = idx - b * kE;
    int src = ei[b * 2 * kE + e];
    int dst = ei[b * 2 * kE + kE + e];
    atomicAdd(&g_gout[b * kNN + dst], ew[idx] * g_s[b * kNN + src]);
}

// ---------------- global mean/var over gout -------------------------------
__global__ __launch_bounds__(256) void stats_kernel() {
    int i = blockIdx.x * blockDim.x + threadIdx.x;
    double s = 0.0, s2 = 0.0;
    for (int k = i; k < kB * kNN; k += gridDim.x * blockDim.x) {
        double v = (double)g_gout[k];
        s += v; s2 += v * v;
    }
#pragma unroll
    for (int o = 16; o > 0; o >>= 1) {
        s  += __shfl_xor_sync(~0u, s, o);
        s2 += __shfl_xor_sync(~0u, s2, o);
    }
    __shared__ double ws[8][2];
    int w = threadIdx.x >> 5;
    if ((threadIdx.x & 31) == 0) { ws[w][0] = s; ws[w][1] = s2; }
    __syncthreads();
    if (threadIdx.x == 0) {
        double a = 0, b2 = 0;
        for (int k = 0; k < 8; k++) { a += ws[k][0]; b2 += ws[k][1]; }
        atomicAdd(&g_red[0], a);
        atomicAdd(&g_red[1], b2);
    }
}

// ---------------- batchnorm + rank-1 output --------------------------------
__global__ void out_kernel(const float* __restrict__ bng,
                           const float* __restrict__ bnb,
                           const float* __restrict__ lw,
                           const float* __restrict__ lb,
                           float* __restrict__ out) {
    int idx = blockIdx.x * blockDim.x + threadIdx.x;
    if (idx >= kRows * kD) return;
    int d = idx & 127;
    int t = (idx >> 7) & 127;
    int n = (idx >> 14) & 63;
    int b = idx >> 20;
    const double inv_n = 1.0 / (double)(kB * kNN);
    double m = g_red[0] * inv_n;
    double var = g_red[1] * inv_n - m * m;
    double rs = 1.0 / sqrt(var + 1e-5);
    float gv = g_gout[b * kNN + t * kNA + n];
    float norm = (float)(((double)gv - m) * rs) * bng[0] + bnb[0];
    out[idx] = norm * lw[d] + lb[d];
}

// ---------------- launch ---------------------------------------------------
extern "C" void kernel_launch(void* const* d_in, const int* in_sizes, int n_in,
                              void* d_out, int out_size) {
    const float* feat  = (const float*)d_in[0];
    const int*   eidx  = (const int*)d_in[1];
    const float* ew    = (const float*)d_in[2];
    const float* histw = (const float*)d_in[3];
    const float* histb = (const float*)d_in[4];
    const float* wq    = (const float*)d_in[5];
    const float* bq    = (const float*)d_in[6];
    const float* wk    = (const float*)d_in[7];
    const float* bk    = (const float*)d_in[8];
    const float* wv    = (const float*)d_in[9];
    const float* bv    = (const float*)d_in[10];
    const float* wo    = (const float*)d_in[11];
    const float* bo    = (const float*)d_in[12];
    const float* ln1g  = (const float*)d_in[13];
    const float* ln1b  = (const float*)d_in[14];
    const float* fw1   = (const float*)d_in[15];
    const float* fb1   = (const float*)d_in[16];
    const float* fw2   = (const float*)d_in[17];
    const float* fb2   = (const float*)d_in[18];
    const float* ln2g  = (const float*)d_in[19];
    const float* ln2b  = (const float*)d_in[20];
    const float* bng   = (const float*)d_in[21];
    const float* bnb   = (const float*)d_in[22];
    const float* lgw   = (const float*)d_in[23];
    const float* lgb   = (const float*)d_in[24];
    float* out = (float*)d_out;

    float *pe, *pq, *pk, *pv, *pao, *ph1, *ptmp, *pff;
    cudaGetSymbolAddress((void**)&pe,  g_e);
    cudaGetSymbolAddress((void**)&pq,  g_q);
    cudaGetSymbolAddress((void**)&pk,  g_k);
    cudaGetSymbolAddress((void**)&pv,  g_v);
    cudaGetSymbolAddress((void**)&pao, g_ao);
    cudaGetSymbolAddress((void**)&ph1, g_h1);
    cudaGetSymbolAddress((void**)&ptmp, g_tmp);
    cudaGetSymbolAddress((void**)&pff, g_ff);

    zero_kernel<<<(kB * kNN + 255) / 256, 256>>>();
    hist_pe_kernel<<<kRows, 128>>>(feat, histw, histb);

    dim3 gD(kD / 64, kRows / 64);     // N=128
    dim3 gF(kDFF / 64, kRows / 64);   // N=512

    for (int l = 0; l < kL; l++) {
        const float* wql = wq + l * kD * kD;
        const float* wkl = wk + l * kD * kD;
        const float* wvl = wv + l * kD * kD;
        const float* wol = wo + l * kD * kD;
        sgemm64<false><<<gD, 256>>>(pe, wql, bq + l * kD, pq, kRows, kD, kD);
        sgemm64<false><<<gD, 256>>>(pe, wkl, bk + l * kD, pk, kRows, kD, kD);
        sgemm64<false><<<gD, 256>>>(pe, wvl, bv + l * kD, pv, kRows, kD, kD);
        attn_kernel<<<dim3(kB * kNA, kH), 128>>>();
        sgemm64<false><<<gD, 256>>>(pao, wol, bo + l * kD, ptmp, kRows, kD, kD);
        ln_kernel<<<kRows, 128>>>(pe, ptmp, ln1g + l * kD, ln1b + l * kD, ph1);
        sgemm64<true><<<gF, 256>>>(ph1, fw1 + l * kD * kDFF, fb1 + l * kDFF,
                                   pff, kRows, kDFF, kD);
        sgemm64<false><<<gD, 256>>>(pff, fw2 + l * kDFF * kD, fb2 + l * kD,
                                    ptmp, kRows, kD, kDFF);
        ln_kernel<<<kRows, 128>>>(ph1, ptmp, ln2g + l * kD, ln2b + l * kD, pe);
    }

    s_kernel<<<kRows, 128>>>();
    edge_kernel<<<(kB * kE + 255) / 256, 256>>>(eidx, ew);
    stats_kernel<<<64, 256>>>();
    out_kernel<<<(kRows * kD + 255) / 256, 256>>>(bng, bnb, lgw, lgb, out);
}

// round 4
// speedup vs baseline: 1.5090x; 1.5090x over previous
#include <cuda_runtime.h>
#include <cuda_bf16.h>
#include <math.h>
#include <stdint.h>

static constexpr int kB = 4, kNA = 64, kT = 128, kD = 128, kH = 8, kL = 3;
static constexpr int kDFF = 512, kE = 65536, kNN = kT * kNA, kDH = kD / kH;
static constexpr int kRows = kB * kNA * kT;   // 32768

// ---------------- scratch (device globals; no runtime allocation) ----------
__device__ float g_x  [kRows * kD];
__device__ float g_e  [kRows * kD];
__device__ float g_qkv[kRows * 384];
__device__ float g_ao [kRows * kD];
__device__ float g_h1 [kRows * kD];
__device__ float g_tmp[kRows * kD];
__device__ float g_ff [kRows * kDFF];
__device__ float g_s   [kB * kNN];
__device__ float g_gout[kB * kNN];
__device__ double g_red[2];

// transposed bf16-split weights: per layer block of 196608 elems:
//   [0]      QKV^T : 384 x 128
//   [49152]  O^T   : 128 x 128
//   [65536]  FF1^T : 512 x 128
//   [131072] FF2^T : 128 x 512
static constexpr int kWL = 196608;
__device__ __nv_bfloat16 g_wth[kL * kWL];
__device__ __nv_bfloat16 g_wtl[kL * kWL];
__device__ float g_bqkv[kL * 384];

// ====================== weight conversion (fp32 -> bf16 hi/lo, transposed) =
__global__ void wconv_kernel(const float* __restrict__ W, int K, int N,
                             __nv_bfloat16* __restrict__ dh,
                             __nv_bfloat16* __restrict__ dl) {
    int i = blockIdx.x * blockDim.x + threadIdx.x;
    if (i >= K * N) return;
    int k = i / N, n = i - k * N;
    float x = W[i];
    __nv_bfloat16 h = __float2bfloat16(x);
    __nv_bfloat16 l = __float2bfloat16(x - __bfloat162float(h));
    dh[n * K + k] = h;
    dl[n * K + k] = l;
}

__global__ void bqkv_kernel(const float* __restrict__ bq,
                            const float* __restrict__ bk,
                            const float* __restrict__ bv) {
    int i = blockIdx.x * blockDim.x + threadIdx.x;
    if (i >= kL * 384) return;
    int l = i / 384, j = i - l * 384;
    float v = (j < 128) ? bq[l * 128 + j]
            : (j < 256) ? bk[l * 128 + j - 128]
                        : bv[l * 128 + j - 256];
    g_bqkv[i] = v;
}

// ====================== bf16-split MMA GEMM ================================
// C(MxN) = A(MxK, fp32) * W(KxN) + bias ; W given transposed [N][K] bf16 hi/lo.
// CTA tile 128x128, 8 warps (4x2), warp tile 32x64, K staged by 64.
// smem rows padded to 72 bf16 (conflict-free fragment LDS).
static constexpr int kPad = 72;
static constexpr int kTileBytes = 128 * kPad * 2;          // 18432
static constexpr int kGemmSmem = 4 * kTileBytes;           // 73728

__device__ __forceinline__ void mma16816(float* c, const uint32_t* a,
                                         const uint32_t* b) {
    asm volatile(
        "mma.sync.aligned.m16n8k16.row.col.f32.bf16.bf16.f32 "
        "{%0,%1,%2,%3}, {%4,%5,%6,%7}, {%8,%9}, {%0,%1,%2,%3};"
        : "+f"(c[0]), "+f"(c[1]), "+f"(c[2]), "+f"(c[3])
        : "r"(a[0]), "r"(a[1]), "r"(a[2]), "r"(a[3]), "r"(b[0]), "r"(b[1]));
}

template <bool RELU>
__global__ __launch_bounds__(256) void gemm_mma(
        const float* __restrict__ A, const __nv_bfloat16* __restrict__ Bh,
        const __nv_bfloat16* __restrict__ Bl, const float* __restrict__ bias,
        float* __restrict__ C, int N, int K) {
    extern __shared__ __nv_bfloat16 sm[];
    __nv_bfloat16* Ah = sm;
    __nv_bfloat16* Al = sm + 128 * kPad;
    __nv_bfloat16* Bsh = sm + 2 * 128 * kPad;
    __nv_bfloat16* Bsl = sm + 3 * 128 * kPad;

    const int tid = threadIdx.x;
    const int wid = tid >> 5, lane = tid & 31;
    const int g = lane >> 2, tig = lane & 3;
    const int mw = wid >> 1, nw = wid & 1;      // 4 x 2 warp grid
    const int m0 = blockIdx.y * 128, n0 = blockIdx.x * 128;

    float acc[2][8][4];
#pragma unroll
    for (int i = 0; i < 2; i++)
#pragma unroll
        for (int j = 0; j < 8; j++)
#pragma unroll
            for (int t = 0; t < 4; t++) acc[i][j][t] = 0.f;

    const int stages = K >> 6;
    for (int s = 0; s < stages; s++) {
        const int k0 = s << 6;
        if (s) __syncthreads();
        // A: 128 rows x 32 float2 -> hi/lo bf16 pairs
#pragma unroll 4
        for (int i = tid; i < 128 * 32; i += 256) {
            int r = i >> 5, cp = i & 31;
            float2 a = *(const float2*)&A[(size_t)(m0 + r) * K + k0 + cp * 2];
            __nv_bfloat16 h0 = __float2bfloat16(a.x);
            __nv_bfloat16 h1 = __float2bfloat16(a.y);
            __nv_bfloat16 l0 = __float2bfloat16(a.x - __bfloat162float(h0));
            __nv_bfloat16 l1 = __float2bfloat16(a.y - __bfloat162float(h1));
            __nv_bfloat162 hp = {h0, h1}, lp = {l0, l1};
            *(uint32_t*)&Ah[r * kPad + cp * 2] = *(uint32_t*)&hp;
            *(uint32_t*)&Al[r * kPad + cp * 2] = *(uint32_t*)&lp;
        }
        // B: copy pre-split bf16
#pragma unroll 4
        for (int i = tid; i < 128 * 32; i += 256) {
            int r = i >> 5, cp = i & 31;
            size_t gidx = (size_t)(n0 + r) * K + k0 + cp * 2;
            *(uint32_t*)&Bsh[r * kPad + cp * 2] = *(const uint32_t*)&Bh[gidx];
            *(uint32_t*)&Bsl[r * kPad + cp * 2] = *(const uint32_t*)&Bl[gidx];
        }
        __syncthreads();

#pragma unroll
        for (int ks = 0; ks < 4; ks++) {
            const int kk = ks << 4;
            uint32_t ah[2][4], al[2][4];
#pragma unroll
            for (int mt = 0; mt < 2; mt++) {
                int mr = mw * 32 + mt * 16 + g;
                const int c0 = kk + tig * 2, c1 = kk + 8 + tig * 2;
                ah[mt][0] = *(uint32_t*)&Ah[mr * kPad + c0];
                ah[mt][1] = *(uint32_t*)&Ah[(mr + 8) * kPad + c0];
                ah[mt][2] = *(uint32_t*)&Ah[mr * kPad + c1];
                ah[mt][3] = *(uint32_t*)&Ah[(mr + 8) * kPad + c1];
                al[mt][0] = *(uint32_t*)&Al[mr * kPad + c0];
                al[mt][1] = *(uint32_t*)&Al[(mr + 8) * kPad + c0];
                al[mt][2] = *(uint32_t*)&Al[mr * kPad + c1];
                al[mt][3] = *(uint32_t*)&Al[(mr + 8) * kPad + c1];
            }
#pragma unroll
            for (int nt = 0; nt < 8; nt++) {
                int nr = nw * 64 + nt * 8 + g;
                uint32_t bh[2], bl[2];
                bh[0] = *(uint32_t*)&Bsh[nr * kPad + kk + tig * 2];
                bh[1] = *(uint32_t*)&Bsh[nr * kPad + kk + 8 + tig * 2];
                bl[0] = *(uint32_t*)&Bsl[nr * kPad + kk + tig * 2];
                bl[1] = *(uint32_t*)&Bsl[nr * kPad + kk + 8 + tig * 2];
#pragma unroll
                for (int mt = 0; mt < 2; mt++) {
                    mma16816(acc[mt][nt], ah[mt], bh);
                    mma16816(acc[mt][nt], ah[mt], bl);
                    mma16816(acc[mt][nt], al[mt], bh);
                }
            }
        }
    }

    // epilogue
#pragma unroll
    for (int mt = 0; mt < 2; mt++) {
#pragma unroll
        for (int nt = 0; nt < 8; nt++) {
            int col = n0 + nw * 64 + nt * 8 + tig * 2;
            float b0 = bias[col], b1 = bias[col + 1];
            int r0 = m0 + mw * 32 + mt * 16 + g;
            float2 v0, v1;
            v0.x = acc[mt][nt][0] + b0; v0.y = acc[mt][nt][1] + b1;
            v1.x = acc[mt][nt][2] + b0; v1.y = acc[mt][nt][3] + b1;
            if (RELU) {
                v0.x = fmaxf(v0.x, 0.f); v0.y = fmaxf(v0.y, 0.f);
                v1.x = fmaxf(v1.x, 0.f); v1.y = fmaxf(v1.y, 0.f);
            }
            *(float2*)&C[(size_t)r0 * N + col] = v0;
            *(float2*)&C[(size_t)(r0 + 8) * N + col] = v1;
        }
    }
}

// ---------------- zero accumulators --------------------------------------
__global__ void zero_kernel() {
    int i = blockIdx.x * blockDim.x + threadIdx.x;
    if (i < kB * kNN) g_gout[i] = 0.f;
    if (i < 2) g_red[i] = 0.0;
}

// ---------------- hist projection + positional encoding -------------------
__global__ __launch_bounds__(128) void hist_pe_kernel(
        const float* __restrict__ feat, const float* __restrict__ w,
        const float* __restrict__ bias) {
    int row = blockIdx.x;
    int d = threadIdx.x;
    float f0 = feat[row * 3 + 0], f1 = feat[row * 3 + 1], f2 = feat[row * 3 + 2];
    float x = f0 * w[d] + f1 * w[kD + d] + f2 * w[2 * kD + d] + bias[d];
    g_x[row * kD + d] = x;
    int t = row % kT;
    int j = d >> 1;
    float freq = expf(-9.210340371976184f * (float)(2 * j) / (float)kD);
    float ang = (float)t * freq;
    float pe = (d & 1) ? cosf(ang) : sinf(ang);
    g_e[row * kD + d] = x + pe;
}

// ---------------- fused attention per (b*n, h) -----------------------------
__global__ __launch_bounds__(128) void attn_kernel() {
    int bn = blockIdx.x;
    int h  = blockIdx.y;
    int t  = threadIdx.x;
    __shared__ float sk[kT][kDH];
    __shared__ float sv[kT][kDH];
    const float* base = g_qkv + (size_t)(bn * kT + t) * 384;
    const float* kp = base + 128 + h * kDH;
    const float* vp = base + 256 + h * kDH;
#pragma unroll
    for (int i = 0; i < 4; i++) {
        *(float4*)&sk[t][i * 4] = *(const float4*)&kp[i * 4];
        *(float4*)&sv[t][i * 4] = *(const float4*)&vp[i * 4];
    }
    float qr[16];
    const float* qp = base + h * kDH;
#pragma unroll
    for (int i = 0; i < 4; i++)
        *(float4*)&qr[i * 4] = *(const float4*)&qp[i * 4];
    __syncthreads();

    const float scale = 0.25f;
    float m = -1e30f;
    for (int j = 0; j < kT; j++) {
        float a0 = 0, a1 = 0, a2 = 0, a3 = 0;
#pragma unroll
        for (int i = 0; i < 4; i++) {
            a0 += qr[i * 4 + 0] * sk[j][i * 4 + 0];
            a1 += qr[i * 4 + 1] * sk[j][i * 4 + 1];
            a2 += qr[i * 4 + 2] * sk[j][i * 4 + 2];
            a3 += qr[i * 4 + 3] * sk[j][i * 4 + 3];
        }
        m = fmaxf(m, (a0 + a1 + a2 + a3) * scale);
    }
    float sum = 0.f;
    float oacc[16];
#pragma unroll
    for (int i = 0; i < 16; i++) oacc[i] = 0.f;
    for (int j = 0; j < kT; j++) {
        float a0 = 0, a1 = 0, a2 = 0, a3 = 0;
#pragma unroll
        for (int i = 0; i < 4; i++) {
            a0 += qr[i * 4 + 0] * sk[j][i * 4 + 0];
            a1 += qr[i * 4 + 1] * sk[j][i * 4 + 1];
            a2 += qr[i * 4 + 2] * sk[j][i * 4 + 2];
            a3 += qr[i * 4 + 3] * sk[j][i * 4 + 3];
        }
        float p = expf((a0 + a1 + a2 + a3) * scale - m);
        sum += p;
#pragma unroll
        for (int i = 0; i < 16; i++) oacc[i] += p * sv[j][i];
    }
    float inv = 1.f / sum;
    float* op = g_ao + (size_t)(bn * kT + t) * kD + h * kDH;
#pragma unroll
    for (int i = 0; i < 16; i++) op[i] = oacc[i] * inv;
}

// ---------------- fused residual + layernorm (rows of 128) -----------------
__global__ __launch_bounds__(128) void ln_kernel(
        const float* __restrict__ a, const float* __restrict__ r,
        const float* __restrict__ g, const float* __restrict__ b,
        float* __restrict__ out) {
    int row = blockIdx.x, t = threadIdx.x;
    float v = a[row * kD + t] + r[row * kD + t];
    __shared__ float ws[4];
    __shared__ float bc;
    float s = v;
#pragma unroll
    for (int o = 16; o > 0; o >>= 1) s += __shfl_xor_sync(~0u, s, o);
    if ((t & 31) == 0) ws[t >> 5] = s;
    __syncthreads();
    if (t == 0) bc = ws[0] + ws[1] + ws[2] + ws[3];
    __syncthreads();
    float mean = bc * (1.f / kD);
    float dv = v - mean;
    s = dv * dv;
#pragma unroll
    for (int o = 16; o > 0; o >>= 1) s += __shfl_xor_sync(~0u, s, o);
    if ((t & 31) == 0) ws[t >> 5] = s;
    __syncthreads();
    if (t == 0) bc = ws[0] + ws[1] + ws[2] + ws[3];
    __syncthreads();
    float var = bc * (1.f / kD);
    out[row * kD + t] = dv * rsqrtf(var + 1e-5f) * g[t] + b[t];
}

// ---------------- node score ----------------------------------------------
__global__ __launch_bounds__(128) void s_kernel() {
    int row = blockIdx.x, t = threadIdx.x;
    float p = g_e[row * kD + t] * g_x[row * kD + t];
    __shared__ float ws[4];
#pragma unroll
    for (int o = 16; o > 0; o >>= 1) p += __shfl_xor_sync(~0u, p, o);
    if ((t & 31) == 0) ws[t >> 5] = p;
    __syncthreads();
    if (t == 0) {
        float tot = ws[0] + ws[1] + ws[2] + ws[3];
        int b = row / (kNA * kT);
        int rem = row % (kNA * kT);
        int n = rem / kT, tt = rem % kT;
        g_s[b * kNN + tt * kNA + n] = tot;
    }
}

// ---------------- edge segment-sum ----------------------------------------
__global__ void edge_kernel(const int* __restrict__ ei,
                            const float* __restrict__ ew) {
    int idx = blockIdx.x * blockDim.x + threadIdx.x;
    if (idx >= kB * kE) return;
    int b = idx / kE, e = idx - b * kE;
    int src = ei[b * 2 * kE + e];
    int dst = ei[b * 2 * kE + kE + e];
    atomicAdd(&g_gout[b * kNN + dst], ew[idx] * g_s[b * kNN + src]);
}

// ---------------- global mean/var over gout -------------------------------
__global__ __launch_bounds__(256) void stats_kernel() {
    int i = blockIdx.x * blockDim.x + threadIdx.x;
    double s = 0.0, s2 = 0.0;
    for (int k = i; k < kB * kNN; k += gridDim.x * blockDim.x) {
        double v = (double)g_gout[k];
        s += v; s2 += v * v;
    }
#pragma unroll
    for (int o = 16; o > 0; o >>= 1) {
        s  += __shfl_xor_sync(~0u, s, o);
        s2 += __shfl_xor_sync(~0u, s2, o);
    }
    __shared__ double ws[8][2];
    int w = threadIdx.x >> 5;
    if ((threadIdx.x & 31) == 0) { ws[w][0] = s; ws[w][1] = s2; }
    __syncthreads();
    if (threadIdx.x == 0) {
        double a = 0, b2 = 0;
        for (int k = 0; k < 8; k++) { a += ws[k][0]; b2 += ws[k][1]; }
        atomicAdd(&g_red[0], a);
        atomicAdd(&g_red[1], b2);
    }
}

// ---------------- batchnorm + rank-1 output --------------------------------
__global__ void out_kernel(const float* __restrict__ bng,
                           const float* __restrict__ bnb,
                           const float* __restrict__ lw,
                           const float* __restrict__ lb,
                           float* __restrict__ out) {
    int idx = blockIdx.x * blockDim.x + threadIdx.x;
    if (idx >= kRows * kD) return;
    int d = idx & 127;
    int t = (idx >> 7) & 127;
    int n = (idx >> 14) & 63;
    int b = idx >> 20;
    const double inv_n = 1.0 / (double)(kB * kNN);
    double m = g_red[0] * inv_n;
    double var = g_red[1] * inv_n - m * m;
    double rs = 1.0 / sqrt(var + 1e-5);
    float gv = g_gout[b * kNN + t * kNA + n];
    float norm = (float)(((double)gv - m) * rs) * bng[0] + bnb[0];
    out[idx] = norm * lw[d] + lb[d];
}

// ---------------- launch ---------------------------------------------------
extern "C" void kernel_launch(void* const* d_in, const int* in_sizes, int n_in,
                              void* d_out, int out_size) {
    const float* feat  = (const float*)d_in[0];
    const int*   eidx  = (const int*)d_in[1];
    const float* ew    = (const float*)d_in[2];
    const float* histw = (const float*)d_in[3];
    const float* histb = (const float*)d_in[4];
    const float* wq    = (const float*)d_in[5];
    const float* bq    = (const float*)d_in[6];
    const float* wk    = (const float*)d_in[7];
    const float* bk    = (const float*)d_in[8];
    const float* wv    = (const float*)d_in[9];
    const float* bv    = (const float*)d_in[10];
    const float* wo    = (const float*)d_in[11];
    const float* bo    = (const float*)d_in[12];
    const float* ln1g  = (const float*)d_in[13];
    const float* ln1b  = (const float*)d_in[14];
    const float* fw1   = (const float*)d_in[15];
    const float* fb1   = (const float*)d_in[16];
    const float* fw2   = (const float*)d_in[17];
    const float* fb2   = (const float*)d_in[18];
    const float* ln2g  = (const float*)d_in[19];
    const float* ln2b  = (const float*)d_in[20];
    const float* bng   = (const float*)d_in[21];
    const float* bnb   = (const float*)d_in[22];
    const float* lgw   = (const float*)d_in[23];
    const float* lgb   = (const float*)d_in[24];
    float* out = (float*)d_out;

    float *pe, *pqkv, *pao, *ph1, *ptmp, *pff, *pbqkv;
    __nv_bfloat16 *pwh, *pwl;
    cudaGetSymbolAddress((void**)&pe,   g_e);
    cudaGetSymbolAddress((void**)&pqkv, g_qkv);
    cudaGetSymbolAddress((void**)&pao,  g_ao);
    cudaGetSymbolAddress((void**)&ph1,  g_h1);
    cudaGetSymbolAddress((void**)&ptmp, g_tmp);
    cudaGetSymbolAddress((void**)&pff,  g_ff);
    cudaGetSymbolAddress((void**)&pwh,  g_wth);
    cudaGetSymbolAddress((void**)&pwl,  g_wtl);
    cudaGetSymbolAddress((void**)&pbqkv, g_bqkv);

    cudaFuncSetAttribute(gemm_mma<false>,
                         cudaFuncAttributeMaxDynamicSharedMemorySize, kGemmSmem);
    cudaFuncSetAttribute(gemm_mma<true>,
                         cudaFuncAttributeMaxDynamicSharedMemorySize, kGemmSmem);

    zero_kernel<<<(kB * kNN + 255) / 256, 256>>>();
    bqkv_kernel<<<(kL * 384 + 255) / 256, 256>>>(bq, bk, bv);

    // weight conversion (transposed bf16 hi/lo)
    for (int l = 0; l < kL; l++) {
        const int base = l * kWL;
        wconv_kernel<<<64, 256>>>(wq + l * kD * kD, kD, kD,
                                  pwh + base, pwl + base);
        wconv_kernel<<<64, 256>>>(wk + l * kD * kD, kD, kD,
                                  pwh + base + 128 * 128, pwl + base + 128 * 128);
        wconv_kernel<<<64, 256>>>(wv + l * kD * kD, kD, kD,
                                  pwh + base + 256 * 128, pwl + base + 256 * 128);
        wconv_kernel<<<64, 256>>>(wo + l * kD * kD, kD, kD,
                                  pwh + base + 49152, pwl + base + 49152);
        wconv_kernel<<<256, 256>>>(fw1 + l * kD * kDFF, kD, kDFF,
                                   pwh + base + 65536, pwl + base + 65536);
        wconv_kernel<<<256, 256>>>(fw2 + l * kDFF * kD, kDFF, kD,
                                   pwh + base + 131072, pwl + base + 131072);
    }

    hist_pe_kernel<<<kRows, 128>>>(feat, histw, histb);

    const int MT = kRows / 128;  // 256 M tiles
    for (int l = 0; l < kL; l++) {
        const int base = l * kWL;
        // QKV fused: N=384
        gemm_mma<false><<<dim3(3, MT), 256, kGemmSmem>>>(
            pe, pwh + base, pwl + base, pbqkv + l * 384, pqkv, 384, kD);
        attn_kernel<<<dim3(kB * kNA, kH), 128>>>();
        // O: N=128
        gemm_mma<false><<<dim3(1, MT), 256, kGemmSmem>>>(
            pao, pwh + base + 49152, pwl + base + 49152, bo + l * kD,
            ptmp, kD, kD);
        ln_kernel<<<kRows, 128>>>(pe, ptmp, ln1g + l * kD, ln1b + l * kD, ph1);
        // FF1: N=512, relu
        gemm_mma<true><<<dim3(4, MT), 256, kGemmSmem>>>(
            ph1, pwh + base + 65536, pwl + base + 65536, fb1 + l * kDFF,
            pff, kDFF, kD);
        // FF2: N=128, K=512
        gemm_mma<false><<<dim3(1, MT), 256, kGemmSmem>>>(
            pff, pwh + base + 131072, pwl + base + 131072, fb2 + l * kD,
            ptmp, kD, kDFF);
        ln_kernel<<<kRows, 128>>>(ph1, ptmp, ln2g + l * kD, ln2b + l * kD, pe);
    }

    s_kernel<<<kRows, 128>>>();
    edge_kernel<<<(kB * kE + 255) / 256, 256>>>(eidx, ew);
    stats_kernel<<<64, 256>>>();
    out_kernel<<<(kRows * kD + 255) / 256, 256>>>(bng, bnb, lgw, lgb, out);
}

// round 6
// speedup vs baseline: 1.5872x; 1.0518x over previous
#include <cuda_runtime.h>
#include <cuda_bf16.h>
#include <math.h>
#include <stdint.h>

static constexpr int kB = 4, kNA = 64, kT = 128, kD = 128, kH = 8, kL = 3;
static constexpr int kDFF = 512, kE = 65536, kNN = kT * kNA, kDH = kD / kH;
static constexpr int kRows = kB * kNA * kT;   // 32768

// ---------------- scratch (device globals; no runtime allocation) ----------
__device__ float g_x  [kRows * kD];
__device__ float g_e  [kRows * kD];
__device__ float g_qkv[kRows * 384];
__device__ float g_h1 [kRows * kD];
__device__ float g_tmp[kRows * kD];
__device__ float g_s   [kB * kNN];
__device__ float g_gout[kB * kNN];
__device__ double g_red[2];

// bf16 hi/lo split activations (A operands for GEMMs)
__device__ __nv_bfloat16 g_eh [kRows * kD],  g_el [kRows * kD];
__device__ __nv_bfloat16 g_aoh[kRows * kD],  g_aol[kRows * kD];
__device__ __nv_bfloat16 g_h1h[kRows * kD],  g_h1l[kRows * kD];
__device__ __nv_bfloat16 g_ffh[kRows * kDFF], g_ffl[kRows * kDFF];

// transposed bf16-split weights, per layer block of 196608 elems:
//   [0] QKV^T 384x128 | [49152] O^T 128x128 | [65536] FF1^T 512x128 | [131072] FF2^T 128x512
static constexpr int kWL = 196608;
__device__ __nv_bfloat16 g_wth[kL * kWL];
__device__ __nv_bfloat16 g_wtl[kL * kWL];
__device__ float g_bqkv[kL * 384];

__device__ __forceinline__ void split2(float x, __nv_bfloat16& h, __nv_bfloat16& l) {
    h = __float2bfloat16(x);
    l = __float2bfloat16(x - __bfloat162float(h));
}

// ====================== fused weight conversion ============================
__global__ __launch_bounds__(256) void wconv_all(
        const float* __restrict__ wq, const float* __restrict__ wk,
        const float* __restrict__ wv, const float* __restrict__ wo,
        const float* __restrict__ fw1, const float* __restrict__ fw2) {
    int i = blockIdx.x * blockDim.x + threadIdx.x;
    if (i >= kL * kWL) return;
    int l = i / kWL, off = i - l * kWL;
    const float* W; int N, n, k;
    if (off < 49152) {
        int m = off >> 14, o2 = off & 16383;
        W = (m == 0 ? wq : m == 1 ? wk : wv) + l * 16384;
        n = o2 >> 7; k = o2 & 127; N = 128;
    } else if (off < 65536) {
        int o2 = off - 49152;
        W = wo + l * 16384; n = o2 >> 7; k = o2 & 127; N = 128;
    } else if (off < 131072) {
        int o2 = off - 65536;
        W = fw1 + l * 65536; n = o2 >> 7; k = o2 & 127; N = 512;
    } else {
        int o2 = off - 131072;
        W = fw2 + l * 65536; n = o2 >> 9; k = o2 & 511; N = 128;
    }
    __nv_bfloat16 h, lo;
    split2(W[(size_t)k * N + n], h, lo);
    g_wth[i] = h; g_wtl[i] = lo;
}

__global__ void bqkv_kernel(const float* __restrict__ bq,
                            const float* __restrict__ bk,
                            const float* __restrict__ bv) {
    int i = blockIdx.x * blockDim.x + threadIdx.x;
    if (i >= kL * 384) return;
    int l = i / 384, j = i - l * 384;
    float v = (j < 128) ? bq[l * 128 + j]
            : (j < 256) ? bk[l * 128 + j - 128]
                        : bv[l * 128 + j - 256];
    g_bqkv[i] = v;
}

// ====================== bf16-split MMA GEMM (ldmatrix + cp.async) ==========
// C(MxN) = A(MxK) * W(KxN) + bias. A given as bf16 hi/lo [M][K]; W transposed
// hi/lo [N][K]. CTA tile 128x128, 8 warps (4x2), warp 32x64, K chunk 64,
// double-buffered smem. Row pad: 72 bf16 = 144B.
static constexpr int kPadB = 144;
static constexpr int kArrB = 128 * kPadB;      // 18432 per array
static constexpr int kBufB = 4 * kArrB;        // 73728 per buffer
static constexpr int kGemmSmem = 2 * kBufB;    // 147456

#define LDSM4(r, addr) \
    asm volatile("ldmatrix.sync.aligned.m8n8.x4.shared.b16 {%0,%1,%2,%3}, [%4];" \
        : "=r"((r)[0]), "=r"((r)[1]), "=r"((r)[2]), "=r"((r)[3]) : "r"(addr))

__device__ __forceinline__ void mma16816(float* c, const uint32_t* a,
                                         const uint32_t* b) {
    asm volatile(
        "mma.sync.aligned.m16n8k16.row.col.f32.bf16.bf16.f32 "
        "{%0,%1,%2,%3}, {%4,%5,%6,%7}, {%8,%9}, {%0,%1,%2,%3};"
        : "+f"(c[0]), "+f"(c[1]), "+f"(c[2]), "+f"(c[3])
        : "r"(a[0]), "r"(a[1]), "r"(a[2]), "r"(a[3]), "r"(b[0]), "r"(b[1]));
}

template <int OUT>   // 0: fp32 C + bias ; 1: relu + bf16 hi/lo split out
__global__ __launch_bounds__(256) void gemm_mma(
        const __nv_bfloat16* __restrict__ Ahg, const __nv_bfloat16* __restrict__ Alg,
        const __nv_bfloat16* __restrict__ Bhg, const __nv_bfloat16* __restrict__ Blg,
        const float* __restrict__ bias, float* __restrict__ C,
        __nv_bfloat16* __restrict__ Ch, __nv_bfloat16* __restrict__ Cl,
        int N, int K) {
    extern __shared__ char smem[];
    const uint32_t sbase = (uint32_t)__cvta_generic_to_shared(smem);
    const int tid = threadIdx.x;
    const int wid = tid >> 5, lane = tid & 31;
    const int g = lane >> 2, tig = lane & 3;
    const int mw = wid >> 1, nw = wid & 1;
    const int m0 = blockIdx.y * 128, n0 = blockIdx.x * 128;

    float acc[2][8][4];
#pragma unroll
    for (int i = 0; i < 2; i++)
#pragma unroll
        for (int j = 0; j < 8; j++)
#pragma unroll
            for (int t = 0; t < 4; t++) acc[i][j][t] = 0.f;

    const int stages = K >> 6;

    // per-lane ldmatrix offsets
    const uint32_t aRowOff = (uint32_t)((lane & 15) * kPadB + (lane >> 4) * 16);
    const int bRow = (lane & 7) + ((lane >> 4) & 1) * 8;
    const uint32_t bOff = (uint32_t)(bRow * kPadB + ((lane >> 3) & 1) * 16);

    // cp.async fill of one stage into buffer b
    auto issue = [&](int s, int b) {
#pragma unroll
        for (int it = 0; it < 16; it++) {
            const int arr = it >> 2;
            const int j = tid + ((it & 3) << 8);   // 0..1023
            const int r = j >> 3, c = j & 7;
            const __nv_bfloat16* gp;
            if (arr == 0)      gp = Ahg + (size_t)(m0 + r) * K + (s << 6) + c * 8;
            else if (arr == 1) gp = Alg + (size_t)(m0 + r) * K + (s << 6) + c * 8;
            else if (arr == 2) gp = Bhg + (size_t)(n0 + r) * K + (s << 6) + c * 8;
            else               gp = Blg + (size_t)(n0 + r) * K + (s << 6) + c * 8;
            uint32_t dp = sbase + b * kBufB + arr * kArrB + r * kPadB + c * 16;
            asm volatile("cp.async.ca.shared.global [%0], [%1], 16;"
                         :: "r"(dp), "l"(gp));
        }
        asm volatile("cp.async.commit_group;");
    };

    issue(0, 0);
    for (int s = 0; s < stages; s++) {
        if (s + 1 < stages) {
            issue(s + 1, (s + 1) & 1);
            asm volatile("cp.async.wait_group 1;");
        } else {
            asm volatile("cp.async.wait_group 0;");
        }
        __syncthreads();

        const uint32_t base = sbase + (s & 1) * kBufB;
        const uint32_t aH = base + (uint32_t)(mw * 32) * kPadB + aRowOff;
        const uint32_t bH = base + 2 * kArrB + (uint32_t)(nw * 64) * kPadB + bOff;
#pragma unroll
        for (int ks = 0; ks < 4; ks++) {
            const uint32_t kb = ks * 32;
            uint32_t ah[2][4], al[2][4];
#pragma unroll
            for (int mt = 0; mt < 2; mt++) {
                LDSM4(ah[mt], aH + mt * 2304 + kb);
                LDSM4(al[mt], aH + kArrB + mt * 2304 + kb);
            }
#pragma unroll
            for (int ntp = 0; ntp < 4; ntp++) {
                uint32_t bh[4], bl[4];
                LDSM4(bh, bH + ntp * 2304 + kb);
                LDSM4(bl, bH + kArrB + ntp * 2304 + kb);
#pragma unroll
                for (int mt = 0; mt < 2; mt++) {
                    mma16816(acc[mt][2 * ntp], ah[mt], bh);
                    mma16816(acc[mt][2 * ntp], ah[mt], bl);
                    mma16816(acc[mt][2 * ntp], al[mt], bh);
                    mma16816(acc[mt][2 * ntp + 1], ah[mt], bh + 2);
                    mma16816(acc[mt][2 * ntp + 1], ah[mt], bl + 2);
                    mma16816(acc[mt][2 * ntp + 1], al[mt], bh + 2);
                }
            }
        }
        __syncthreads();
    }

    // epilogue
#pragma unroll
    for (int mt = 0; mt < 2; mt++) {
#pragma unroll
        for (int nt = 0; nt < 8; nt++) {
            const int col = n0 + nw * 64 + nt * 8 + tig * 2;
            const float b0 = bias[col], b1 = bias[col + 1];
            const int r0 = m0 + mw * 32 + mt * 16 + g;
            float v00 = acc[mt][nt][0] + b0, v01 = acc[mt][nt][1] + b1;
            float v10 = acc[mt][nt][2] + b0, v11 = acc[mt][nt][3] + b1;
            if (OUT == 1) {
                v00 = fmaxf(v00, 0.f); v01 = fmaxf(v01, 0.f);
                v10 = fmaxf(v10, 0.f); v11 = fmaxf(v11, 0.f);
                __nv_bfloat162 h0, l0, h1, l1;
                split2(v00, h0.x, l0.x); split2(v01, h0.y, l0.y);
                split2(v10, h1.x, l1.x); split2(v11, h1.y, l1.y);
                *(__nv_bfloat162*)&Ch[(size_t)r0 * N + col] = h0;
                *(__nv_bfloat162*)&Cl[(size_t)r0 * N + col] = l0;
                *(__nv_bfloat162*)&Ch[(size_t)(r0 + 8) * N + col] = h1;
                *(__nv_bfloat162*)&Cl[(size_t)(r0 + 8) * N + col] = l1;
            } else {
                *(float2*)&C[(size_t)r0 * N + col] = {v00, v01};
                *(float2*)&C[(size_t)(r0 + 8) * N + col] = {v10, v11};
            }
        }
    }
}

// ---------------- zero accumulators --------------------------------------
__global__ void zero_kernel() {
    int i = blockIdx.x * blockDim.x + threadIdx.x;
    if (i < kB * kNN) g_gout[i] = 0.f;
    if (i < 2) g_red[i] = 0.0;
}

// ---------------- hist projection + positional encoding -------------------
__global__ __launch_bounds__(128) void hist_pe_kernel(
        const float* __restrict__ feat, const float* __restrict__ w,
        const float* __restrict__ bias) {
    int row = blockIdx.x;
    int d = threadIdx.x;
    float f0 = feat[row * 3 + 0], f1 = feat[row * 3 + 1], f2 = feat[row * 3 + 2];
    float x = f0 * w[d] + f1 * w[kD + d] + f2 * w[2 * kD + d] + bias[d];
    g_x[row * kD + d] = x;
    int t = row % kT;
    int j = d >> 1;
    float freq = expf(-9.210340371976184f * (float)(2 * j) / (float)kD);
    float ang = (float)t * freq;
    float pe = (d & 1) ? cosf(ang) : sinf(ang);
    float e = x + pe;
    g_e[row * kD + d] = e;
    __nv_bfloat16 h, l;
    split2(e, h, l);
    g_eh[row * kD + d] = h;
    g_el[row * kD + d] = l;
}

// ---------------- fused attention per (b*n, h), online softmax -------------
__global__ __launch_bounds__(128) void attn_kernel() {
    int bn = blockIdx.x;
    int h  = blockIdx.y;
    int t  = threadIdx.x;
    __shared__ float sk[kT][kDH];
    __shared__ float sv[kT][kDH];
    const float* base = g_qkv + (size_t)(bn * kT + t) * 384;
    const float* kp = base + 128 + h * kDH;
    const float* vp = base + 256 + h * kDH;
#pragma unroll
    for (int i = 0; i < 4; i++) {
        *(float4*)&sk[t][i * 4] = *(const float4*)&kp[i * 4];
        *(float4*)&sv[t][i * 4] = *(const float4*)&vp[i * 4];
    }
    float qr[16];
    const float* qp = base + h * kDH;
#pragma unroll
    for (int i = 0; i < 4; i++)
        *(float4*)&qr[i * 4] = *(const float4*)&qp[i * 4];
    __syncthreads();

    const float scale = 0.25f;
    float m = -1e30f, sum = 0.f;
    float oacc[16];
#pragma unroll
    for (int i = 0; i < 16; i++) oacc[i] = 0.f;
    for (int j = 0; j < kT; j++) {
        float a0 = 0, a1 = 0, a2 = 0, a3 = 0;
#pragma unroll
        for (int i = 0; i < 4; i++) {
            a0 += qr[i * 4 + 0] * sk[j][i * 4 + 0];
            a1 += qr[i * 4 + 1] * sk[j][i * 4 + 1];
            a2 += qr[i * 4 + 2] * sk[j][i * 4 + 2];
            a3 += qr[i * 4 + 3] * sk[j][i * 4 + 3];
        }
        float s = (a0 + a1 + a2 + a3) * scale;
        if (s > m) {
            float c = expf(m - s);
            sum *= c;
#pragma unroll
            for (int i = 0; i < 16; i++) oacc[i] *= c;
            m = s;
        }
        float p = expf(s - m);
        sum += p;
#pragma unroll
        for (int i = 0; i < 16; i++) oacc[i] += p * sv[j][i];
    }
    float inv = 1.f / sum;
    size_t off = (size_t)(bn * kT + t) * kD + h * kDH;
#pragma unroll
    for (int i = 0; i < 16; i++) {
        __nv_bfloat16 hh, ll;
        split2(oacc[i] * inv, hh, ll);
        g_aoh[off + i] = hh;
        g_aol[off + i] = ll;
    }
}

// ---------------- fused residual + layernorm + bf16 split ------------------
__global__ __launch_bounds__(128) void ln_kernel(
        const float* __restrict__ a, const float* __restrict__ r,
        const float* __restrict__ g, const float* __restrict__ b,
        float* __restrict__ out, __nv_bfloat16* __restrict__ oh,
        __nv_bfloat16* __restrict__ ol) {
    int row = blockIdx.x, t = threadIdx.x;
    float v = a[row * kD + t] + r[row * kD + t];
    __shared__ float ws[4];
    __shared__ float bc;
    float s = v;
#pragma unroll
    for (int o = 16; o > 0; o >>= 1) s += __shfl_xor_sync(~0u, s, o);
    if ((t & 31) == 0) ws[t >> 5] = s;
    __syncthreads();
    if (t == 0) bc = ws[0] + ws[1] + ws[2] + ws[3];
    __syncthreads();
    float mean = bc * (1.f / kD);
    float dv = v - mean;
    s = dv * dv;
#pragma unroll
    for (int o = 16; o > 0; o >>= 1) s += __shfl_xor_sync(~0u, s, o);
    if ((t & 31) == 0) ws[t >> 5] = s;
    __syncthreads();
    if (t == 0) bc = ws[0] + ws[1] + ws[2] + ws[3];
    __syncthreads();
    float var = bc * (1.f / kD);
    float res = dv * rsqrtf(var + 1e-5f) * g[t] + b[t];
    out[row * kD + t] = res;
    __nv_bfloat16 hh, ll;
    split2(res, hh, ll);
    oh[row * kD + t] = hh;
    ol[row * kD + t] = ll;
}

// ---------------- node score ----------------------------------------------
__global__ __launch_bounds__(128) void s_kernel() {
    int row = blockIdx.x, t = threadIdx.x;
    float p = g_e[row * kD + t] * g_x[row * kD + t];
    __shared__ float ws[4];
#pragma unroll
    for (int o = 16; o > 0; o >>= 1) p += __shfl_xor_sync(~0u, p, o);
    if ((t & 31) == 0) ws[t >> 5] = p;
    __syncthreads();
    if (t == 0) {
        float tot = ws[0] + ws[1] + ws[2] + ws[3];
        int b = row / (kNA * kT);
        int rem = row % (kNA * kT);
        int n = rem / kT, tt = rem % kT;
        g_s[b * kNN + tt * kNA + n] = tot;
    }
}

// ---------------- edge segment-sum ----------------------------------------
__global__ void edge_kernel(const int* __restrict__ ei,
                            const float* __restrict__ ew) {
    int idx = blockIdx.x * blockDim.x + threadIdx.x;
    if (idx >= kB * kE) return;
    int b = idx / kE, e = idx - b * kE;
    int src = ei[b * 2 * kE + e];
    int dst = ei[b * 2 * kE + kE + e];
    atomicAdd(&g_gout[b * kNN + dst], ew[idx] * g_s[b * kNN + src]);
}

// ---------------- global mean/var over gout -------------------------------
__global__ __launch_bounds__(256) void stats_kernel() {
    int i = blockIdx.x * blockDim.x + threadIdx.x;
    double s = 0.0, s2 = 0.0;
    for (int k = i; k < kB * kNN; k += gridDim.x * blockDim.x) {
        double v = (double)g_gout[k];
        s += v; s2 += v * v;
    }
#pragma unroll
    for (int o = 16; o > 0; o >>= 1) {
        s  += __shfl_xor_sync(~0u, s, o);
        s2 += __shfl_xor_sync(~0u, s2, o);
    }
    __shared__ double ws[8][2];
    int w = threadIdx.x >> 5;
    if ((threadIdx.x & 31) == 0) { ws[w][0] = s; ws[w][1] = s2; }
    __syncthreads();
    if (threadIdx.x == 0) {
        double a = 0, b2 = 0;
        for (int k = 0; k < 8; k++) { a += ws[k][0]; b2 += ws[k][1]; }
        atomicAdd(&g_red[0], a);
        atomicAdd(&g_red[1], b2);
    }
}

// ---------------- batchnorm + rank-1 output --------------------------------
__global__ void out_kernel(const float* __restrict__ bng,
                           const float* __restrict__ bnb,
                           const float* __restrict__ lw,
                           const float* __restrict__ lb,
                           float* __restrict__ out) {
    int idx = blockIdx.x * blockDim.x + threadIdx.x;
    if (idx >= kRows * kD) return;
    int d = idx & 127;
    int t = (idx >> 7) & 127;
    int n = (idx >> 14) & 63;
    int b = idx >> 20;
    const double inv_n = 1.0 / (double)(kB * kNN);
    double m = g_red[0] * inv_n;
    double var = g_red[1] * inv_n - m * m;
    double rs = 1.0 / sqrt(var + 1e-5);
    float gv = g_gout[b * kNN + t * kNA + n];
    float norm = (float)(((double)gv - m) * rs) * bng[0] + bnb[0];
    out[idx] = norm * lw[d] + lb[d];
}

// ---------------- launch ---------------------------------------------------
extern "C" void kernel_launch(void* const* d_in, const int* in_sizes, int n_in,
                              void* d_out, int out_size) {
    const float* feat  = (const float*)d_in[0];
    const int*   eidx  = (const int*)d_in[1];
    const float* ew    = (const float*)d_in[2];
    const float* histw = (const float*)d_in[3];
    const float* histb = (const float*)d_in[4];
    const float* wq    = (const float*)d_in[5];
    const float* bq    = (const float*)d_in[6];
    const float* wk    = (const float*)d_in[7];
    const float* bk    = (const float*)d_in[8];
    const float* wv    = (const float*)d_in[9];
    const float* bv    = (const float*)d_in[10];
    const float* wo    = (const float*)d_in[11];
    const float* bo    = (const float*)d_in[12];
    const float* ln1g  = (const float*)d_in[13];
    const float* ln1b  = (const float*)d_in[14];
    const float* fw1   = (const float*)d_in[15];
    const float* fb1   = (const float*)d_in[16];
    const float* fw2   = (const float*)d_in[17];
    const float* fb2   = (const float*)d_in[18];
    const float* ln2g  = (const float*)d_in[19];
    const float* ln2b  = (const float*)d_in[20];
    const float* bng   = (const float*)d_in[21];
    const float* bnb   = (const float*)d_in[22];
    const float* lgw   = (const float*)d_in[23];
    const float* lgb   = (const float*)d_in[24];
    float* out = (float*)d_out;

    float *pe, *pqkv, *ph1, *ptmp, *pbqkv;
    __nv_bfloat16 *pwh, *pwl, *peh, *pel, *paoh, *paol, *ph1h, *ph1l, *pffh, *pffl;
    cudaGetSymbolAddress((void**)&pe,   g_e);
    cudaGetSymbolAddress((void**)&pqkv, g_qkv);
    cudaGetSymbolAddress((void**)&ph1,  g_h1);
    cudaGetSymbolAddress((void**)&ptmp, g_tmp);
    cudaGetSymbolAddress((void**)&pwh,  g_wth);
    cudaGetSymbolAddress((void**)&pwl,  g_wtl);
    cudaGetSymbolAddress((void**)&pbqkv, g_bqkv);
    cudaGetSymbolAddress((void**)&peh,  g_eh);
    cudaGetSymbolAddress((void**)&pel,  g_el);
    cudaGetSymbolAddress((void**)&paoh, g_aoh);
    cudaGetSymbolAddress((void**)&paol, g_aol);
    cudaGetSymbolAddress((void**)&ph1h, g_h1h);
    cudaGetSymbolAddress((void**)&ph1l, g_h1l);
    cudaGetSymbolAddress((void**)&pffh, g_ffh);
    cudaGetSymbolAddress((void**)&pffl, g_ffl);

    cudaFuncSetAttribute(gemm_mma<0>,
                         cudaFuncAttributeMaxDynamicSharedMemorySize, kGemmSmem);
    cudaFuncSetAttribute(gemm_mma<1>,
                         cudaFuncAttributeMaxDynamicSharedMemorySize, kGemmSmem);

    zero_kernel<<<(kB * kNN + 255) / 256, 256>>>();
    bqkv_kernel<<<(kL * 384 + 255) / 256, 256>>>(bq, bk, bv);
    wconv_all<<<(kL * kWL + 255) / 256, 256>>>(wq, wk, wv, wo, fw1, fw2);
    hist_pe_kernel<<<kRows, 128>>>(feat, histw, histb);

    const int MT = kRows / 128;  // 256 M tiles
    for (int l = 0; l < kL; l++) {
        const int base = l * kWL;
        // QKV fused: N=384, K=128
        gemm_mma<0><<<dim3(3, MT), 256, kGemmSmem>>>(
            peh, pel, pwh + base, pwl + base, pbqkv + l * 384,
            pqkv, nullptr, nullptr, 384, 128);
        attn_kernel<<<dim3(kB * kNA, kH), 128>>>();
        // O: N=128, K=128
        gemm_mma<0><<<dim3(1, MT), 256, kGemmSmem>>>(
            paoh, paol, pwh + base + 49152, pwl + base + 49152, bo + l * kD,
            ptmp, nullptr, nullptr, 128, 128);
        ln_kernel<<<kRows, 128>>>(pe, ptmp, ln1g + l * kD, ln1b + l * kD,
                                  ph1, ph1h, ph1l);
        // FF1: N=512, K=128, relu + split out
        gemm_mma<1><<<dim3(4, MT), 256, kGemmSmem>>>(
            ph1h, ph1l, pwh + base + 65536, pwl + base + 65536, fb1 + l * kDFF,
            nullptr, pffh, pffl, 512, 128);
        // FF2: N=128, K=512
        gemm_mma<0><<<dim3(1, MT), 256, kGemmSmem>>>(
            pffh, pffl, pwh + base + 131072, pwl + base + 131072, fb2 + l * kD,
            ptmp, nullptr, nullptr, 128, 512);
        ln_kernel<<<kRows, 128>>>(ph1, ptmp, ln2g + l * kD, ln2b + l * kD,
                                  pe, peh, pel);
    }

    s_kernel<<<kRows, 128>>>();
    edge_kernel<<<(kB * kE + 255) / 256, 256>>>(eidx, ew);
    stats_kernel<<<64, 256>>>();
    out_kernel<<<(kRows * kD + 255) / 256, 256>>>(bng, bnb, lgw, lgb, out);
}